// round 17
// baseline (speedup 1.0000x reference)
#include <cuda_runtime.h>
#include <cuda_bf16.h>
#include <cstdint>
#include <math.h>

#define DD 1024
#define B_ROWS 128
#define C_ROWS 1000
#define C_PAD 1024
#define N_ROWS (B_ROWS + C_ROWS)   // 1128
#define N_PAD 1152                 // 18 * 64
#define EPSF 1e-6f

// ---------------- scratch (__device__, zero-initialized) ----------------
__device__ float g_bx[B_ROWS];
__device__ float g_bm[C_ROWS];
__device__ float g_sa[N_ROWS];                // ||a||^2 per input row (fp32)
__device__ float g_partZ[16][N_PAD];          // per-coltile partial ||z||^2
__device__ __nv_bfloat16 g_Ah[N_PAD * DD];    // [x;mu] hi bf16 (padded rows zero)
__device__ __nv_bfloat16 g_Al[N_PAD * DD];    // [x;mu] lo bf16
__device__ __nv_bfloat16 g_BhT[DD * DD];      // tril(L)^T hi: [col][k]
__device__ __nv_bfloat16 g_BlT[DD * DD];      // tril(L)^T lo
__device__ __nv_bfloat16 g_Yh[B_ROWS * DD];   // Y = x@trilL, hi bf16 only
__device__ __nv_bfloat16 g_Mh[C_PAD * DD];    // M = mu@trilL, hi (rows 1000.. stay 0)

// ---------------- helpers (family-generic PTX: sm_80-era) ----------------
__device__ __forceinline__ uint32_t smem_to_u32(const void* p) {
    uint32_t a;
    asm("{ .reg .u64 t; cvta.to.shared.u64 t, %1; cvt.u32.u64 %0, t; }"
        : "=r"(a) : "l"(p));
    return a;
}

#define CP16(dst, src) \
    asm volatile("cp.async.cg.shared.global [%0], [%1], 16;" \
        :: "r"(dst), "l"(src) : "memory")
#define CP_COMMIT() asm volatile("cp.async.commit_group;" ::: "memory")
#define CP_WAIT0()  asm volatile("cp.async.wait_group 0;" ::: "memory")

#define LDSM4(r0, r1, r2, r3, addr) \
    asm volatile("ldmatrix.sync.aligned.m8n8.x4.shared.b16 {%0,%1,%2,%3}, [%4];" \
        : "=r"(r0), "=r"(r1), "=r"(r2), "=r"(r3) : "r"(addr))

#define MMA16816(d, a, b) \
    asm volatile("mma.sync.aligned.m16n8k16.row.col.f32.bf16.bf16.f32 " \
        "{%0,%1,%2,%3}, {%4,%5,%6,%7}, {%8,%9}, {%0,%1,%2,%3};" \
        : "+f"((d)[0]), "+f"((d)[1]), "+f"((d)[2]), "+f"((d)[3]) \
        : "r"((a)[0]), "r"((a)[1]), "r"((a)[2]), "r"((a)[3]), \
          "r"((b)[0]), "r"((b)[1]))

__device__ __forceinline__ void split_bf16(float v, __nv_bfloat16& h, __nv_bfloat16& l) {
    h = __float2bfloat16_rn(v);
    l = __float2bfloat16_rn(v - __bfloat162float(h));
}

// ---------------------------------------------------------------------------
// conv_all: merged conversion kernel.
//  blocks [0, N_PAD):        conv_A — one block per row of [x;mu]:
//                            bf16 hi/lo + stats (||a||^2, beta.a)
//  blocks [N_PAD, N_PAD+256): conv_LT — tril(L) masked/transposed/split,
//                            64x64 tile per block.
// ---------------------------------------------------------------------------
__global__ __launch_bounds__(256) void conv_all(
    const float* __restrict__ x, const float* __restrict__ mu,
    const float* __restrict__ beta, const float* __restrict__ L) {
    const int tid = threadIdx.x;

    if (blockIdx.x < N_PAD) {
        // ---- conv_A ----
        const int row = blockIdx.x;
        const int c4 = tid * 4;

        float4 v = make_float4(0.f, 0.f, 0.f, 0.f);
        if (row < B_ROWS)       v = *reinterpret_cast<const float4*>(&x[(size_t)row * DD + c4]);
        else if (row < N_ROWS)  v = *reinterpret_cast<const float4*>(&mu[(size_t)(row - B_ROWS) * DD + c4]);
        float4 bt = *reinterpret_cast<const float4*>(&beta[c4]);

        float vv[4] = {v.x, v.y, v.z, v.w};
        float bb[4] = {bt.x, bt.y, bt.z, bt.w};
        __nv_bfloat16 h[4], l[4];
        float sa = 0.f, sb = 0.f;
        #pragma unroll
        for (int i = 0; i < 4; i++) {
            split_bf16(vv[i], h[i], l[i]);
            sa += vv[i] * vv[i];
            sb += bb[i] * vv[i];
        }
        *reinterpret_cast<uint2*>(&g_Ah[(size_t)row * DD + c4]) = *reinterpret_cast<uint2*>(h);
        *reinterpret_cast<uint2*>(&g_Al[(size_t)row * DD + c4]) = *reinterpret_cast<uint2*>(l);

        #pragma unroll
        for (int off = 16; off; off >>= 1) {
            sa += __shfl_down_sync(0xffffffffu, sa, off);
            sb += __shfl_down_sync(0xffffffffu, sb, off);
        }
        __shared__ float red[2][8];
        int w = tid >> 5, lane = tid & 31;
        if (lane == 0) { red[0][w] = sa; red[1][w] = sb; }
        __syncthreads();
        if (tid == 0 && row < N_ROWS) {
            float SA = 0.f, SB = 0.f;
            #pragma unroll
            for (int i = 0; i < 8; i++) { SA += red[0][i]; SB += red[1][i]; }
            g_sa[row] = SA;
            if (row < B_ROWS) g_bx[row] = SB;
            else              g_bm[row - B_ROWS] = SB;
        }
    } else {
        // ---- conv_LT ----
        __shared__ float tile[64][65];
        const int bid = blockIdx.x - N_PAD;       // 0..255
        const int bC = (bid & 15) * 64;           // col base
        const int bR = (bid >> 4) * 64;           // k base

        #pragma unroll
        for (int i = 0; i < 16; i++) {
            int idx = tid + i * 256;
            int r = idx >> 6, c = idx & 63;
            float v = L[(size_t)(bR + r) * DD + bC + c];
            if (bC + c > bR + r) v = 0.f;   // tril mask
            tile[r][c] = v;
        }
        __syncthreads();
        #pragma unroll
        for (int i = 0; i < 16; i++) {
            int idx = tid + i * 256;
            int c = idx >> 6, r = idx & 63;
            float v = tile[r][c];
            __nv_bfloat16 h, l;
            split_bf16(v, h, l);
            size_t o = (size_t)(bC + c) * DD + bR + r;
            g_BhT[o] = h;
            g_BlT[o] = l;
        }
    }
}

// ---------------------------------------------------------------------------
// Kernel 1 (warp MMA): Z = A @ tril(L), split-bf16 3-term (hh + hl + lh).
// BM=64, BN=64, BK=32, 128 threads. Pair-balanced tril skip.
// Epilogue: exact fp32 row-norm partials -> g_partZ; Z stored as bf16 hi only.
// ---------------------------------------------------------------------------
#define TILE_B (64 * 40)
#define STAGE_B (4 * TILE_B)

__global__ __launch_bounds__(128) void k1_mma() {
    __shared__ __align__(16) __nv_bfloat16 sm[2][STAGE_B];
    __shared__ float zred[64][8];

    const int tid   = threadIdx.x;
    const int lane  = tid & 31;
    const int warp  = tid >> 5;
    const int warpm = warp & 1;
    const int warpn = warp >> 1;
    const int pairid  = blockIdx.x;        // 0..7
    const int rowBase = blockIdx.y * 64;

    const uint32_t smbase = smem_to_u32(sm);

    #pragma unroll 1
    for (int phase = 0; phase < 2; phase++) {
        const int ct = phase ? (15 - pairid) : pairid;
        const int colBase = ct * 64;
        const int NIT = (DD - colBase) >> 5;

        const __nv_bfloat16* srcb[8];
        uint32_t dsto[8];
        #pragma unroll
        for (int t = 0; t < 8; t++) {
            int tl  = t >> 1;
            int row = ((t & 1) << 5) + (tid >> 2);
            int c4  = tid & 3;
            const __nv_bfloat16* g;
            int grow;
            if      (tl == 0) { g = g_Ah;  grow = rowBase + row; }
            else if (tl == 1) { g = g_Al;  grow = rowBase + row; }
            else if (tl == 2) { g = g_BhT; grow = colBase + row; }
            else              { g = g_BlT; grow = colBase + row; }
            srcb[t] = g + (size_t)grow * DD + c4 * 8;
            dsto[t] = (uint32_t)(tl * (TILE_B * 2) + row * 80 + c4 * 16);
        }

        float acc[2][4][4];
        #pragma unroll
        for (int i = 0; i < 2; i++)
            #pragma unroll
            for (int j = 0; j < 4; j++)
                #pragma unroll
                for (int r = 0; r < 4; r++) acc[i][j][r] = 0.f;

        __syncthreads();   // protect smem (tiles + zred) across phases

        {
            #pragma unroll
            for (int t = 0; t < 8; t++) CP16(smbase + dsto[t], srcb[t] + colBase);
            CP_COMMIT();
        }

        const uint32_t a_row_off = (uint32_t)((warpm * 32 + (lane & 15)) * 80);
        const uint32_t b_row_off = (uint32_t)((warpn * 32 + (lane & 15)) * 80);
        const uint32_t k_lane_off = (uint32_t)(((lane >> 4) & 1) * 16);

        for (int it = 0; it < NIT; it++) {
            CP_WAIT0();
            __syncthreads();
            if (it + 1 < NIT) {
                uint32_t sbn = smbase + ((it + 1) & 1) * (STAGE_B * 2);
                int k0 = colBase + (it + 1) * 32;
                #pragma unroll
                for (int t = 0; t < 8; t++) CP16(sbn + dsto[t], srcb[t] + k0);
                CP_COMMIT();
            }

            const uint32_t bufb = smbase + (it & 1) * (STAGE_B * 2);

            #pragma unroll
            for (int k16 = 0; k16 < 2; k16++) {
                const uint32_t kb = (uint32_t)(k16 * 32) + k_lane_off;

                uint32_t ah[2][4], al[2][4];
                #pragma unroll
                for (int mt = 0; mt < 2; mt++) {
                    uint32_t ad = bufb + a_row_off + (uint32_t)(mt * 16 * 80) + kb;
                    LDSM4(ah[mt][0], ah[mt][1], ah[mt][2], ah[mt][3], ad);
                    LDSM4(al[mt][0], al[mt][1], al[mt][2], al[mt][3], ad + TILE_B * 2);
                }
                uint32_t bh[4][2], bl[4][2];
                #pragma unroll
                for (int nt2 = 0; nt2 < 2; nt2++) {
                    uint32_t bd = bufb + 2 * (TILE_B * 2) + b_row_off
                                + (uint32_t)(nt2 * 16 * 80) + kb;
                    uint32_t r0, r1, r2, r3;
                    LDSM4(r0, r1, r2, r3, bd);
                    bh[nt2 * 2 + 0][0] = r0; bh[nt2 * 2 + 0][1] = r2;
                    bh[nt2 * 2 + 1][0] = r1; bh[nt2 * 2 + 1][1] = r3;
                    LDSM4(r0, r1, r2, r3, bd + TILE_B * 2);
                    bl[nt2 * 2 + 0][0] = r0; bl[nt2 * 2 + 0][1] = r2;
                    bl[nt2 * 2 + 1][0] = r1; bl[nt2 * 2 + 1][1] = r3;
                }
                #pragma unroll
                for (int mt = 0; mt < 2; mt++)
                    #pragma unroll
                    for (int nt = 0; nt < 4; nt++) {
                        MMA16816(acc[mt][nt], ah[mt], bh[nt]);
                        MMA16816(acc[mt][nt], ah[mt], bl[nt]);
                        MMA16816(acc[mt][nt], al[mt], bh[nt]);
                    }
            }
        }

        // ---- epilogue: exact fp32 row-norm partials + bf16-hi store ----
        const int pidx = (warpn << 2) | (lane & 3);
        #pragma unroll
        for (int mt = 0; mt < 2; mt++) {
            #pragma unroll
            for (int h = 0; h < 2; h++) {
                int rl = warpm * 32 + mt * 16 + (lane >> 2) + h * 8;
                float s = 0.f;
                #pragma unroll
                for (int nt = 0; nt < 4; nt++) {
                    float v0 = acc[mt][nt][h * 2], v1 = acc[mt][nt][h * 2 + 1];
                    s += v0 * v0 + v1 * v1;
                }
                zred[rl][pidx] = s;
            }
        }

        #pragma unroll
        for (int mt = 0; mt < 2; mt++) {
            #pragma unroll
            for (int nt = 0; nt < 4; nt++) {
                int gm = rowBase + warpm * 32 + mt * 16 + (lane >> 2);
                int gn = colBase + warpn * 32 + nt * 8 + (lane & 3) * 2;
                #pragma unroll
                for (int h = 0; h < 2; h++) {
                    int gr = gm + h * 8;
                    __nv_bfloat162 hh;
                    hh.x = __float2bfloat16_rn(acc[mt][nt][h * 2]);
                    hh.y = __float2bfloat16_rn(acc[mt][nt][h * 2 + 1]);
                    if (gr < B_ROWS)
                        *reinterpret_cast<__nv_bfloat162*>(&g_Yh[(size_t)gr * DD + gn]) = hh;
                    else if (gr < N_ROWS)
                        *reinterpret_cast<__nv_bfloat162*>(&g_Mh[(size_t)(gr - B_ROWS) * DD + gn]) = hh;
                }
            }
        }

        __syncthreads();
        if (tid < 64) {
            float s = 0.f;
            #pragma unroll
            for (int p = 0; p < 8; p++) s += zred[tid][p];
            g_partZ[ct][rowBase + tid] = s;
        }
    }
}

// ---------------------------------------------------------------------------
// k_out (warp MMA): G = Yh @ Mh^T (hi terms only), fused epilogue.
// Prologue folds k_norm: per-block norms for its 32 b-rows / 32 c-cols
// computed from g_partZ + eps*g_sa into smem.
// BM=32, BN=32, BK=32, 128 threads. Grid (32, 4) = 128 blocks.
// ---------------------------------------------------------------------------
#define KO_TILE 1280              // 32 * 40 bf16 elems per tile
#define KO_STAGE (2 * KO_TILE)    // Yh, Mh only

__global__ __launch_bounds__(128) void k_out_mma(
    const float* __restrict__ lmbda_p, const float* __restrict__ scale_p,
    float* __restrict__ out) {
    __shared__ __align__(16) __nv_bfloat16 sm[2][KO_STAGE];
    __shared__ float s_nP[32], s_nQ[32];

    const int tid   = threadIdx.x;
    const int lane  = tid & 31;
    const int warp  = tid >> 5;
    const int warpm = warp & 1;
    const int warpn = warp >> 1;
    const int rowBase = blockIdx.y * 32;   // b
    const int colBase = blockIdx.x * 32;   // c

    const uint32_t smbase = smem_to_u32(sm);

    const __nv_bfloat16* srcb[2];
    uint32_t dsto[2];
    #pragma unroll
    for (int t = 0; t < 2; t++) {
        int ci = tid + t * 128;           // 0..255
        int tl = ci >> 7;                 // 0: Yh, 1: Mh
        int row = (ci & 127) >> 2;        // 0..31
        int c4  = ci & 3;
        const __nv_bfloat16* g;
        int grow;
        if (tl == 0) { g = g_Yh; grow = rowBase + row; }
        else         { g = g_Mh; grow = colBase + row; }
        srcb[t] = g + (size_t)grow * DD + c4 * 8;
        dsto[t] = (uint32_t)(tl * (KO_TILE * 2) + row * 80 + c4 * 16);
    }

    float acc[2][4];
    #pragma unroll
    for (int j = 0; j < 2; j++)
        #pragma unroll
        for (int r = 0; r < 4; r++) acc[j][r] = 0.f;

    {
        #pragma unroll
        for (int t = 0; t < 2; t++) CP16(smbase + dsto[t], srcb[t]);
        CP_COMMIT();
    }

    // ---- prologue: per-block norm computation (replaces k_norm kernel) ----
    if (tid < 64) {
        int gr = (tid < 32) ? (rowBase + tid) : (B_ROWS + colBase + (tid - 32));
        float s = 0.f;
        if (gr < N_ROWS) {
            #pragma unroll
            for (int ct = 0; ct < 16; ct++) s += g_partZ[ct][gr];
            s += EPSF * g_sa[gr];
        }
        if (tid < 32) s_nP[tid] = s;
        else          s_nQ[tid - 32] = s;
    }

    const uint32_t a_row_off = (uint32_t)((warpm * 16 + (lane & 15)) * 80);
    const uint32_t b_row_off = (uint32_t)((warpn * 16 + (lane & 15)) * 80);
    const uint32_t k_lane_off = (uint32_t)(((lane >> 4) & 1) * 16);

    const int NIT = DD / 32;   // 32
    for (int it = 0; it < NIT; it++) {
        CP_WAIT0();
        __syncthreads();
        if (it + 1 < NIT) {
            uint32_t sbn = smbase + ((it + 1) & 1) * (KO_STAGE * 2);
            int k0 = (it + 1) * 32;
            #pragma unroll
            for (int t = 0; t < 2; t++) CP16(sbn + dsto[t], srcb[t] + k0);
            CP_COMMIT();
        }
        const uint32_t bufb = smbase + (it & 1) * (KO_STAGE * 2);

        #pragma unroll
        for (int k16 = 0; k16 < 2; k16++) {
            const uint32_t kb = (uint32_t)(k16 * 32) + k_lane_off;

            uint32_t ah[4];
            LDSM4(ah[0], ah[1], ah[2], ah[3], bufb + a_row_off + kb);

            uint32_t bh[2][2];
            {
                uint32_t r0, r1, r2, r3;
                LDSM4(r0, r1, r2, r3, bufb + (KO_TILE * 2) + b_row_off + kb);
                bh[0][0] = r0; bh[0][1] = r2;
                bh[1][0] = r1; bh[1][1] = r3;
            }
            #pragma unroll
            for (int nt = 0; nt < 2; nt++)
                MMA16816(acc[nt], ah, bh[nt]);
        }
    }

    // fused epilogue (norms from smem)
    const float lmbda = *lmbda_p;
    const float scale = *scale_p;
    #pragma unroll
    for (int nt = 0; nt < 2; nt++) {
        int gm = rowBase + warpm * 16 + (lane >> 2);
        int gn = colBase + warpn * 16 + nt * 8 + (lane & 3) * 2;
        #pragma unroll
        for (int h = 0; h < 2; h++) {
            int b = gm + h * 8;
            float np = s_nP[b - rowBase];
            float bx = g_bx[b];
            #pragma unroll
            for (int e = 0; e < 2; e++) {
                int c = gn + e;
                if (c < C_ROWS) {
                    float G = acc[nt][h * 2 + e];
                    float quad = np + s_nQ[c - colBase] - 2.f * G;
                    float bd = bx - g_bm[c];
                    out[(size_t)b * C_ROWS + c] =
                        -scale * (sqrtf(quad + EPSF) + lmbda * sqrtf(bd * bd + EPSF));
                }
            }
        }
    }
}

// ---------------------------------------------------------------------------
extern "C" void kernel_launch(void* const* d_in, const int* in_sizes, int n_in,
                              void* d_out, int out_size) {
    const float* x     = (const float*)d_in[0];
    const float* mu    = (const float*)d_in[1];
    const float* beta  = (const float*)d_in[2];
    const float* L     = (const float*)d_in[3];
    const float* lmbda = (const float*)d_in[4];
    const float* scale = (const float*)d_in[5];
    float* out = (float*)d_out;

    conv_all<<<N_PAD + 256, 256>>>(x, mu, beta, L);

    k1_mma<<<dim3(8, 18), 128>>>();

    k_out_mma<<<dim3(32, 4), 128>>>(lmbda, scale, out);
}